// round 2
// baseline (speedup 1.0000x reference)
#include <cuda_runtime.h>

// Problem constants
#define Bn 4
#define Tn 64
#define Fn 32
#define Nn 512
#define Hn 64
#define SROWS 288            // 3*F (X taps 0..2) + 3*H (Sz taps 0..2)
#define COLS_PER_CTA 16
#define CTAS_PER_B 32        // 512 / 16
#define NCTAS (Bn * CTAS_PER_B)   // 128 <= 148 SMs, 1 CTA/SM -> all resident
#define NTHREADS 256
#define MB 32                // m-chunk for the big GEMM
#define RPT 18               // 288 / 16 rows per thread

// Persistent global state (allocation-free: __device__ arrays)
__device__ __align__(16) float g_state[2][Bn][SROWS][Nn];   // double-buffered tap state
__device__ __align__(16) float g_zbuf[2][Bn][Hn][Nn];       // z(t-1)
__device__ unsigned g_count = 0;
__device__ unsigned g_sense = 0;

// Sense-reversing grid barrier. Number of calls per launch MUST be even so
// g_sense returns to 0 for the next launch / graph replay.
__device__ __forceinline__ void grid_barrier(unsigned* lsense) {
    __syncthreads();
    if (threadIdx.x == 0) {
        __threadfence();
        unsigned s = (*lsense) ^ 1u;
        *lsense = s;
        unsigned old = atomicAdd(&g_count, 1u);
        if (old == NCTAS - 1u) {
            atomicExch(&g_count, 0u);
            __threadfence();
            atomicExch(&g_sense, s);
        } else {
            while (atomicAdd(&g_sense, 0u) != s) { __nanosleep(64); }
            __threadfence();
        }
    }
    __syncthreads();
}

// Shared memory layout (floats)
#define OFF_WA      0               // aW: 64*128 = 8192
#define OFF_WB      8192            // bW: 64*256 = 16384
#define OFF_BIAS    24576           // 64
#define OFF_STATE   24640           // 288 x 36 (padded) = 10368
#define OFF_S       35008           // 32 x 16 = 512
#define OFF_Y       35520           // 288 x 16 = 4608
#define OFF_X       40128           // 32 x 16 = 512
#define OFF_Z       40640           // 64 x 16 = 1024
#define SMEM_FLOATS 41664
#define SMEM_BYTES  (SMEM_FLOATS * 4)

__global__ void __launch_bounds__(NTHREADS, 1)
hs_db_kernel(const float* __restrict__ x,      // (B,T,F,N)
             const float* __restrict__ z0,     // (B,H,N)
             const float* __restrict__ S,      // (B,T,1,N,N)
             const float* __restrict__ aW,     // (H,1,K,F)
             const float* __restrict__ bW,     // (H,1,K,H)
             const float* __restrict__ xBias,  // (H,1)
             const float* __restrict__ zBias,  // (H,1)
             float* __restrict__ out)          // (B,T,H,N)
{
    extern __shared__ float sm[];
    float* sWa    = sm + OFF_WA;
    float* sWb    = sm + OFF_WB;
    float* sbias  = sm + OFF_BIAS;
    float* sstate = sm + OFF_STATE;   // [288][36]
    float* sS     = sm + OFF_S;       // [32][16]
    float* sY     = sm + OFF_Y;       // [288][16]
    float* sx     = sm + OFF_X;       // [32][16]
    float* sz     = sm + OFF_Z;       // [64][16]

    const int tid   = threadIdx.x;
    const int b     = blockIdx.x / CTAS_PER_B;
    const int col0  = (blockIdx.x % CTAS_PER_B) * COLS_PER_CTA;
    const int c     = tid & 15;
    const int rg    = tid >> 4;          // 0..15
    const int lane8 = tid & 7;
    const int rbase = tid >> 3;          // 0..31

    // Load weights / biases once (constant over t)
    for (int i = tid; i < Hn * 128; i += NTHREADS) sWa[i] = aW[i];
    for (int i = tid; i < Hn * 256; i += NTHREADS) sWb[i] = bW[i];
    if (tid < Hn) sbias[tid] = xBias[tid] + zBias[tid];

    // Init state buffer 0: taps zero, zprev = z0   (column-local)
    for (int i = tid; i < SROWS * COLS_PER_CTA; i += NTHREADS) {
        int r = i >> 4, cc = i & 15;
        g_state[0][b][r][col0 + cc] = 0.0f;
    }
    for (int i = tid; i < Hn * COLS_PER_CTA; i += NTHREADS) {
        int g = i >> 4, cc = i & 15;
        g_zbuf[0][b][g][col0 + cc] = z0[(b * Hn + g) * Nn + col0 + cc];
    }

    unsigned lsense = 0;
    grid_barrier(&lsense);   // barrier #1

    for (int t = 0; t < Tn; ++t) {
        const int cur = t & 1;
        const int nxt = cur ^ 1;
        const float* Sbt = S + (size_t)(b * Tn + t) * Nn * Nn;
        const float* xbt = x + (size_t)(b * Tn + t) * Fn * Nn;

        // Stage x(t) and z(t-1) column slices
        for (int i = tid; i < Fn * 16; i += NTHREADS) {
            int f = i >> 4, cc = i & 15;
            sx[i] = xbt[f * Nn + col0 + cc];
        }
        for (int i = tid; i < Hn * 16; i += NTHREADS) {
            int g = i >> 4, cc = i & 15;
            sz[i] = g_zbuf[cur][b][g][col0 + cc];
        }

        // Phase 1: Y[288,16] = state[288,512] @ S[:, col0:col0+16]
        float acc[RPT];
#pragma unroll
        for (int r = 0; r < RPT; ++r) acc[r] = 0.0f;

        for (int m0 = 0; m0 < Nn; m0 += MB) {
            __syncthreads();
            // S tile: [32][16]
#pragma unroll
            for (int j = 0; j < 2; ++j) {
                int idx = tid + j * NTHREADS;           // 0..511
                int mm = idx >> 4, cc = idx & 15;
                sS[idx] = Sbt[(size_t)(m0 + mm) * Nn + col0 + cc];
            }
            // state tile: 288 rows x 32 floats (float4 per thread)
#pragma unroll
            for (int it = 0; it < 9; ++it) {
                int r = rbase + it * 32;
                const float4 v = *reinterpret_cast<const float4*>(
                    &g_state[cur][b][r][m0 + lane8 * 4]);
                float* d = &sstate[r * 36 + lane8 * 4];
                d[0] = v.x; d[1] = v.y; d[2] = v.z; d[3] = v.w;
            }
            __syncthreads();

            const float* srow = &sstate[rg * RPT * 36];
#pragma unroll
            for (int mm = 0; mm < MB; ++mm) {
                float sv = sS[mm * 16 + c];
#pragma unroll
                for (int r = 0; r < RPT; ++r)
                    acc[r] = fmaf(srow[r * 36 + mm], sv, acc[r]);
            }
        }
        // Store Y to smem
#pragma unroll
        for (int r = 0; r < RPT; ++r)
            sY[(rg * RPT + r) * 16 + c] = acc[r];
        __syncthreads();

        // Phase 2: pre[h,c] = bias + sum_k aW[h,k,:]*Xtap_k + sum_k bW[h,k,:]*Sztap_k
        const int hq = rg;   // 0..15; thread owns h = hq + 16*i
        float pre[4];
#pragma unroll
        for (int i = 0; i < 4; ++i) pre[i] = sbias[hq + 16 * i];

        // X taps: k=0 -> x(t), k=1..3 -> Y rows 32*(k-1)+f
#pragma unroll
        for (int k = 0; k < 4; ++k) {
            const float* src = (k == 0) ? sx : (sY + (32 * (k - 1)) * 16);
#pragma unroll 8
            for (int f = 0; f < Fn; ++f) {
                float v = src[f * 16 + c];
#pragma unroll
                for (int i = 0; i < 4; ++i)
                    pre[i] = fmaf(sWa[(hq + 16 * i) * 128 + k * 32 + f], v, pre[i]);
            }
        }
        // Sz taps: k=0 -> z(t-1), k=1..3 -> Y rows 96+64*(k-1)+g
#pragma unroll
        for (int k = 0; k < 4; ++k) {
            const float* src = (k == 0) ? sz : (sY + (96 + 64 * (k - 1)) * 16);
#pragma unroll 8
            for (int g = 0; g < Hn; ++g) {
                float v = src[g * 16 + c];
#pragma unroll
                for (int i = 0; i < 4; ++i)
                    pre[i] = fmaf(sWb[(hq + 16 * i) * 256 + k * 64 + g], v, pre[i]);
            }
        }

        // z = tanh(pre): write output + zbuf for next step
#pragma unroll
        for (int i = 0; i < 4; ++i) {
            float zv = tanhf(pre[i]);
            int h = hq + 16 * i;
            out[(((size_t)b * Tn + t) * Hn + h) * Nn + col0 + c] = zv;
            g_zbuf[nxt][b][h][col0 + c] = zv;
        }

        // State shift for t+1 (column-local):
        //  rows 0..31   <- x(t)
        //  rows 32..95  <- Y[0..63]    (Xnew taps 1,2)
        //  rows 96..159 <- z(t-1)      (Sz tap0 for next tail)
        //  rows 160..287<- Y[96..223]  (Sznew taps 1,2)
        for (int i = tid; i < SROWS * 16; i += NTHREADS) {
            int r = i >> 4, cc = i & 15;
            float v;
            if (r < 32)        v = sx[r * 16 + cc];
            else if (r < 96)   v = sY[(r - 32) * 16 + cc];
            else if (r < 160)  v = sz[(r - 96) * 16 + cc];
            else               v = sY[(r - 64) * 16 + cc];
            g_state[nxt][b][r][col0 + cc] = v;
        }

        grid_barrier(&lsense);   // barriers #2..#65
    }

    grid_barrier(&lsense);       // barrier #66 (parity: even count per launch)
}

extern "C" void kernel_launch(void* const* d_in, const int* in_sizes, int n_in,
                              void* d_out, int out_size) {
    const float* x     = (const float*)d_in[0];
    const float* z0    = (const float*)d_in[1];
    const float* S     = (const float*)d_in[2];
    const float* aW    = (const float*)d_in[3];
    const float* bW    = (const float*)d_in[4];
    const float* xBias = (const float*)d_in[5];
    const float* zBias = (const float*)d_in[6];
    float* out = (float*)d_out;

    cudaFuncSetAttribute(hs_db_kernel,
                         cudaFuncAttributeMaxDynamicSharedMemorySize, SMEM_BYTES);
    hs_db_kernel<<<NCTAS, NTHREADS, SMEM_BYTES>>>(x, z0, S, aW, bW, xBias, zBias, out);
}

// round 3
// speedup vs baseline: 1.3284x; 1.3284x over previous
#include <cuda_runtime.h>
#include <cstdint>

// Problem constants
#define Bn 4
#define Tn 64
#define Fn 32
#define Nn 512
#define Hn 64
#define SROWS 288            // 3*F (X taps) + 3*H (Sz taps), pre-multiplied state
#define COLS_PER_CTA 16
#define CTAS_PER_B 32
#define NCTAS (Bn * CTAS_PER_B)   // 128 CTAs, 1/SM, all resident
#define NTHREADS 256
#define MB 32                // k-chunk
#define NCHUNK (Nn / MB)     // 16
#define RPT 9                // rows per thread (9 x 2 cols = 18 outputs)

#define PITCH_ST 36          // state tile pitch (floats)
#define PITCH_V  388         // sV pitch (floats)
#define NV       384         // phase-2 vector length

// smem layout (float offsets)
#define OFF_W      0                         // 64 x 384 = 24576
#define OFF_BIAS   24576                     // 64
#define OFF_STATE  24640                     // 2 x (288*36) = 20736
#define ST_BUF     (SROWS * PITCH_ST)        // 10368
#define OFF_SS     45376                     // 2 x (16*36) = 1152
#define SS_BUF     (16 * PITCH_ST)           // 576
#define OFF_V      46528                     // 16 x 388 = 6208
#define SMEM_FLOATS 52736
#define SMEM_BYTES  (SMEM_FLOATS * 4)        // 210944

// Persistent global state
__device__ __align__(16) float g_state[2][Bn][SROWS][Nn];
__device__ unsigned g_count = 0;
__device__ unsigned g_sense = 0;

__device__ __forceinline__ void grid_barrier(unsigned* lsense) {
    __syncthreads();
    if (threadIdx.x == 0) {
        __threadfence();
        unsigned s = (*lsense) ^ 1u;
        *lsense = s;
        unsigned old = atomicAdd(&g_count, 1u);
        if (old == NCTAS - 1u) {
            atomicExch(&g_count, 0u);
            __threadfence();
            atomicExch(&g_sense, s);
        } else {
            while (atomicAdd(&g_sense, 0u) != s) { __nanosleep(64); }
            __threadfence();
        }
    }
    __syncthreads();
}

__device__ __forceinline__ unsigned long long ffma2(unsigned long long a,
                                                    unsigned long long b,
                                                    unsigned long long c) {
    unsigned long long d;
    asm("fma.rn.f32x2 %0, %1, %2, %3;" : "=l"(d) : "l"(a), "l"(b), "l"(c));
    return d;
}
__device__ __forceinline__ float upsum(unsigned long long p) {
    float lo, hi;
    asm("mov.b64 {%0, %1}, %2;" : "=f"(lo), "=f"(hi) : "l"(p));
    return lo + hi;
}
__device__ __forceinline__ void cp_async16(uint32_t dst, const void* src) {
    asm volatile("cp.async.cg.shared.global [%0], [%1], 16;" :: "r"(dst), "l"(src));
}
__device__ __forceinline__ void cp_commit() { asm volatile("cp.async.commit_group;"); }
__device__ __forceinline__ void cp_wait0()  { asm volatile("cp.async.wait_group 0;"); }

__global__ void __launch_bounds__(NTHREADS, 1)
hs_db_kernel(const float* __restrict__ x,      // (B,T,F,N)
             const float* __restrict__ z0,     // (B,H,N)
             const float* __restrict__ S,      // (B,T,1,N,N)
             const float* __restrict__ aW,     // (H,1,K,F)  K*F = 128
             const float* __restrict__ bW,     // (H,1,K,H)  K*H = 256
             const float* __restrict__ xBias,  // (H,1)
             const float* __restrict__ zBias,  // (H,1)
             float* __restrict__ out)          // (B,T,H,N)
{
    extern __shared__ float sm[];
    float* sW    = sm + OFF_W;       // [64][384] = concat(aW row, bW row)
    float* sbias = sm + OFF_BIAS;
    float* sV    = sm + OFF_V;       // [16][388]: [0..31]=x, [32..127]=Y_x, [128..191]=z, [192..383]=Y_sz

    const int tid  = threadIdx.x;
    const int b    = blockIdx.x / CTAS_PER_B;
    const int col0 = (blockIdx.x % CTAS_PER_B) * COLS_PER_CTA;

    // compute mapping (phase 1)
    const int cg  = tid & 7;         // col group -> cols 2cg, 2cg+1
    const int c0  = 2 * cg;
    const int rg9 = tid >> 3;        // 0..31
    const int R0  = rg9 * RPT;
    // loader mapping
    const int seg = tid & 7;         // 16B segment within 128B row chunk
    const int rld = tid >> 3;        // rows rld + 32*it
    // S loader mapping
    const int mmA = tid >> 4;        // 0..15
    const int ccA = tid & 15;
    // phase-2 mapping
    const int hq = tid >> 4;         // 0..15, h in {hq,hq+16,hq+32,hq+48}
    const int cc2 = tid & 15;

    uint32_t smem_base_u32 = (uint32_t)__cvta_generic_to_shared(sm);

    // Load fused weights once: sW[h][0..127]=aW[h], [128..383]=bW[h]
    for (int i = tid; i < Hn * 128; i += NTHREADS) {
        int h = i >> 7, j = i & 127;
        sW[h * NV + j] = aW[i];
    }
    for (int i = tid; i < Hn * 256; i += NTHREADS) {
        int h = i >> 8, j = i & 255;
        sW[h * NV + 128 + j] = bW[i];
    }
    if (tid < Hn) sbias[tid] = xBias[tid] + zBias[tid];

    // Init: state buffer 0 zero (this CTA's columns), sV z-region <- z0
    for (int i = tid; i < SROWS * COLS_PER_CTA; i += NTHREADS) {
        int r = i >> 4, cc = i & 15;
        g_state[0][b][r][col0 + cc] = 0.0f;
    }
    for (int i = tid; i < Hn * COLS_PER_CTA; i += NTHREADS) {
        int g = i >> 4, cc = i & 15;
        sV[cc * PITCH_V + 128 + g] = z0[(b * Hn + g) * Nn + col0 + cc];
    }

    unsigned lsense = 0;
    grid_barrier(&lsense);   // barrier #1

    for (int t = 0; t < Tn; ++t) {
        const int cur = t & 1;
        const int nxt = cur ^ 1;
        const float* Sbt = S + (size_t)(b * Tn + t) * Nn * Nn;
        const float* xbt = x + (size_t)(b * Tn + t) * Fn * Nn;
        const float* gst = &g_state[cur][b][0][0];

        // Stage x(t) -> sV[cc][0..31]  (2 elements per thread)
        {
            int f0 = tid >> 4;                      // 0..15
            sV[ccA * PITCH_V + f0]      = xbt[f0 * Nn + col0 + ccA];
            sV[ccA * PITCH_V + 16 + f0] = xbt[(16 + f0) * Nn + col0 + ccA];
        }

        // ---- Phase 1 pipeline prologue: chunk 0 ----
        float sA = Sbt[(size_t)mmA * Nn + col0 + ccA];
        float sB = Sbt[(size_t)(16 + mmA) * Nn + col0 + ccA];
#pragma unroll
        for (int it = 0; it < RPT; ++it) {
            int r = rld + 32 * it;
            uint32_t dst = smem_base_u32 + (OFF_STATE + r * PITCH_ST + seg * 4) * 4;
            cp_async16(dst, gst + (size_t)r * Nn + seg * 4);
        }
        cp_commit();
        {
            float* ss0 = sm + OFF_SS;
            ss0[ccA * PITCH_ST + mmA] = sA;
            ss0[ccA * PITCH_ST + 16 + mmA] = sB;
        }
        cp_wait0();
        __syncthreads();

        unsigned long long acc[RPT][2];
#pragma unroll
        for (int r = 0; r < RPT; ++r) { acc[r][0] = 0ull; acc[r][1] = 0ull; }

        for (int k = 0; k < NCHUNK; ++k) {
            const int buf = k & 1, nb = buf ^ 1;
            // prefetch chunk k+1
            if (k < NCHUNK - 1) {
                const int m1 = (k + 1) * MB;
                sA = Sbt[(size_t)(m1 + mmA) * Nn + col0 + ccA];
                sB = Sbt[(size_t)(m1 + 16 + mmA) * Nn + col0 + ccA];
#pragma unroll
                for (int it = 0; it < RPT; ++it) {
                    int r = rld + 32 * it;
                    uint32_t dst = smem_base_u32 +
                        (OFF_STATE + nb * ST_BUF + r * PITCH_ST + seg * 4) * 4;
                    cp_async16(dst, gst + (size_t)r * Nn + m1 + seg * 4);
                }
                cp_commit();
            }
            // compute chunk k
            {
                const float* stb = sm + OFF_STATE + buf * ST_BUF;
                const float* ssb = sm + OFF_SS + buf * SS_BUF;
                const float* srow = stb + R0 * PITCH_ST;
                const float* bp0 = ssb + c0 * PITCH_ST;
                const float* bp1 = ssb + (c0 + 1) * PITCH_ST;
#pragma unroll
                for (int mm = 0; mm < MB; mm += 4) {
                    ulonglong2 b0 = *reinterpret_cast<const ulonglong2*>(bp0 + mm);
                    ulonglong2 b1 = *reinterpret_cast<const ulonglong2*>(bp1 + mm);
#pragma unroll
                    for (int r = 0; r < RPT; ++r) {
                        ulonglong2 s = *reinterpret_cast<const ulonglong2*>(
                            srow + r * PITCH_ST + mm);
                        acc[r][0] = ffma2(s.x, b0.x, acc[r][0]);
                        acc[r][1] = ffma2(s.x, b1.x, acc[r][1]);
                        acc[r][0] = ffma2(s.y, b0.y, acc[r][0]);
                        acc[r][1] = ffma2(s.y, b1.y, acc[r][1]);
                    }
                }
            }
            if (k < NCHUNK - 1) {
                cp_wait0();
                float* ssn = sm + OFF_SS + nb * SS_BUF;
                ssn[ccA * PITCH_ST + mmA] = sA;
                ssn[ccA * PITCH_ST + 16 + mmA] = sB;
                __syncthreads();
            }
        }

        // Store Y into transposed sV: row<96 -> j=32+row ; row>=96 -> j=96+row
#pragma unroll
        for (int r = 0; r < RPT; ++r) {
            int row = R0 + r;
            int j = (row < 96) ? (32 + row) : (96 + row);
            sV[c0 * PITCH_V + j]       = upsum(acc[r][0]);
            sV[(c0 + 1) * PITCH_V + j] = upsum(acc[r][1]);
        }
        __syncthreads();

        // ---- Phase 2: pre[h,c] = bias[h] + sum_j sW[h][j] * sV[c][j] ----
        unsigned long long pa[4] = {0ull, 0ull, 0ull, 0ull};
        {
            const float* vp = sV + cc2 * PITCH_V;
#pragma unroll 4
            for (int j = 0; j < NV; j += 4) {
                ulonglong2 v = *reinterpret_cast<const ulonglong2*>(vp + j);
#pragma unroll
                for (int i = 0; i < 4; ++i) {
                    ulonglong2 w = *reinterpret_cast<const ulonglong2*>(
                        sW + (hq + 16 * i) * NV + j);
                    pa[i] = ffma2(w.x, v.x, pa[i]);
                    pa[i] = ffma2(w.y, v.y, pa[i]);
                }
            }
        }
        float zv[4];
#pragma unroll
        for (int i = 0; i < 4; ++i)
            zv[i] = tanhf(sbias[hq + 16 * i] + upsum(pa[i]));

        // ---- State shift for t+1 (reads sV, incl. z(t-1) region) ----
        //  rows 0..31   <- x(t)          (sV j=r)
        //  rows 32..95  <- Y[0..63]      (sV j=32+row-32+... = sV[row])  [row-32 -> j=32+(row-32)=row]
        //  rows 96..159 <- z(t-1)        (sV j=128+(row-96)= row+32)
        //  rows 160..287<- Y[96..223]    (Y row row-64 -> j=96+(row-64)= row+32)
#pragma unroll
        for (int it = 0; it < 18; ++it) {
            int i = tid + it * NTHREADS;
            int r = i >> 4, cc = i & 15;
            int j = (r < 96) ? r : (r + 32);
            g_state[nxt][b][r][col0 + cc] = sV[cc * PITCH_V + j];
        }
        __syncthreads();   // all reads of z(t-1) done before overwrite

        // write z(t) -> out + sV z-region
#pragma unroll
        for (int i = 0; i < 4; ++i) {
            int h = hq + 16 * i;
            out[(((size_t)b * Tn + t) * Hn + h) * Nn + col0 + cc2] = zv[i];
            sV[cc2 * PITCH_V + 128 + h] = zv[i];
        }

        grid_barrier(&lsense);   // barriers #2..#65
    }

    grid_barrier(&lsense);       // barrier #66 (even parity per launch)
}

extern "C" void kernel_launch(void* const* d_in, const int* in_sizes, int n_in,
                              void* d_out, int out_size) {
    const float* x     = (const float*)d_in[0];
    const float* z0    = (const float*)d_in[1];
    const float* S     = (const float*)d_in[2];
    const float* aW    = (const float*)d_in[3];
    const float* bW    = (const float*)d_in[4];
    const float* xBias = (const float*)d_in[5];
    const float* zBias = (const float*)d_in[6];
    float* out = (float*)d_out;

    cudaFuncSetAttribute(hs_db_kernel,
                         cudaFuncAttributeMaxDynamicSharedMemorySize, SMEM_BYTES);
    hs_db_kernel<<<NCTAS, NTHREADS, SMEM_BYTES>>>(x, z0, S, aW, bW, xBias, zBias, out);
}